// round 7
// baseline (speedup 1.0000x reference)
#include <cuda_runtime.h>
#include <cuda_bf16.h>
#include <cstdint>
#include <math.h>

// Sliding-window causal GQA attention via mma.sync (HMMA) bf16 split-precision.
// B=2, S=2048, 8 kv heads x 4 q-heads/kv, D=64, WINDOW=128, fp32 in/out.
// CTA = (b, kvh, 64 queries): M=256 rows (64q x 4h), 192-key window, 16 warps.
// Keys in 3 chunks of 64 with online softmax; per-warp skipping of fully-masked
// 16-key tiles (each warp's queries touch only ~131 of the 192 staged keys).
// Split-bf16: x = hi + lo; 3-term mma products give ~2^-17 accuracy.

namespace {

constexpr int SEQ = 2048;
constexpr float QSCALE = 0.125f * 1.4426950408889634f;  // 1/sqrt(64) * log2(e)

// smem byte offsets: rows of 128B (64 bf16), 16B-chunk XOR swizzle
constexpr int SM_QHI = 0;          // 256 x 128B
constexpr int SM_QLO = 32768;
constexpr int SM_KHI = 65536;      // 192 x 128B
constexpr int SM_KLO = 90112;
constexpr int SM_VHI = 114688;
constexpr int SM_VLO = 139264;
constexpr int SMEM_BYTES = 163840; // 160 KB

__device__ __forceinline__ uint32_t smem_u32(const void* p) {
    uint32_t a;
    asm("{ .reg .u64 t; cvta.to.shared.u64 t, %1; cvt.u32.u64 %0, t; }" : "=r"(a) : "l"(p));
    return a;
}
__device__ __forceinline__ void ldsm4(uint32_t r[4], uint32_t a) {
    asm volatile("ldmatrix.sync.aligned.m8n8.x4.shared.b16 {%0,%1,%2,%3}, [%4];"
                 : "=r"(r[0]), "=r"(r[1]), "=r"(r[2]), "=r"(r[3]) : "r"(a));
}
__device__ __forceinline__ void ldsm4t(uint32_t r[4], uint32_t a) {
    asm volatile("ldmatrix.sync.aligned.m8n8.x4.trans.shared.b16 {%0,%1,%2,%3}, [%4];"
                 : "=r"(r[0]), "=r"(r[1]), "=r"(r[2]), "=r"(r[3]) : "r"(a));
}
__device__ __forceinline__ void mma16816(float d[4], const uint32_t a[4],
                                         uint32_t b0, uint32_t b1) {
    asm volatile(
        "mma.sync.aligned.m16n8k16.row.col.f32.bf16.bf16.f32 "
        "{%0,%1,%2,%3}, {%4,%5,%6,%7}, {%8,%9}, {%0,%1,%2,%3};"
        : "+f"(d[0]), "+f"(d[1]), "+f"(d[2]), "+f"(d[3])
        : "r"(a[0]), "r"(a[1]), "r"(a[2]), "r"(a[3]), "r"(b0), "r"(b1));
}
__device__ __forceinline__ float ex2(float x) {
    float r; asm("ex2.approx.ftz.f32 %0, %1;" : "=f"(r) : "f"(x)); return r;
}
__device__ __forceinline__ void split2(float x, float y, uint32_t& hi, uint32_t& lo) {
    __nv_bfloat162 h = __floats2bfloat162_rn(x, y);
    hi = *reinterpret_cast<uint32_t*>(&h);
    __nv_bfloat162 l = __floats2bfloat162_rn(x - __bfloat162float(h.x),
                                             y - __bfloat162float(h.y));
    lo = *reinterpret_cast<uint32_t*>(&l);
}

__global__ void __launch_bounds__(512, 1)
swa_mma_kernel(const float* __restrict__ Qg,
               const float* __restrict__ Kg,
               const float* __restrict__ Vg,
               float* __restrict__ Og)
{
    extern __shared__ char smem[];
    const uint32_t sb = smem_u32(smem);

    const int tid  = threadIdx.x;
    const int lane = tid & 31;
    const int w    = tid >> 5;
    const int q0   = blockIdx.x * 64;
    const int kvh  = blockIdx.y;
    const int b    = blockIdx.z;

    // ---- stage Q (scaled) as split bf16 hi/lo, swizzled 128B rows ----
    for (int i = tid; i < 256 * 16; i += 512) {
        const int r = i >> 4, c4 = i & 15;
        const float4 v = *reinterpret_cast<const float4*>(
            Qg + ((size_t)(b * SEQ + q0 + (r >> 2)) * 32 + kvh * 4 + (r & 3)) * 64 + c4 * 4);
        uint32_t h0, l0, h1, l1;
        split2(v.x * QSCALE, v.y * QSCALE, h0, l0);
        split2(v.z * QSCALE, v.w * QSCALE, h1, l1);
        const uint32_t off = r * 128 + ((((c4 >> 1) ^ (r & 7))) << 4) + ((c4 & 1) << 3);
        *reinterpret_cast<uint2*>(smem + SM_QHI + off) = make_uint2(h0, h1);
        *reinterpret_cast<uint2*>(smem + SM_QLO + off) = make_uint2(l0, l1);
    }
    // ---- stage K and V (192 key rows: q0-128 .. q0+63), zero-filled below 0 ----
    for (int i = tid; i < 192 * 16; i += 512) {
        const int r = i >> 4, c4 = i & 15;
        const int key = q0 - 128 + r;
        float4 kv = make_float4(0.f, 0.f, 0.f, 0.f), vv = kv;
        if (key >= 0) {
            const size_t gidx = ((size_t)(b * SEQ + key) * 8 + kvh) * 64 + c4 * 4;
            kv = *reinterpret_cast<const float4*>(Kg + gidx);
            vv = *reinterpret_cast<const float4*>(Vg + gidx);
        }
        const uint32_t off = r * 128 + ((((c4 >> 1) ^ (r & 7))) << 4) + ((c4 & 1) << 3);
        uint32_t h0, l0, h1, l1;
        split2(kv.x, kv.y, h0, l0); split2(kv.z, kv.w, h1, l1);
        *reinterpret_cast<uint2*>(smem + SM_KHI + off) = make_uint2(h0, h1);
        *reinterpret_cast<uint2*>(smem + SM_KLO + off) = make_uint2(l0, l1);
        split2(vv.x, vv.y, h0, l0); split2(vv.z, vv.w, h1, l1);
        *reinterpret_cast<uint2*>(smem + SM_VHI + off) = make_uint2(h0, h1);
        *reinterpret_cast<uint2*>(smem + SM_VLO + off) = make_uint2(l0, l1);
    }
    __syncthreads();

    const int g  = lane >> 2, tg = lane & 3;
    const int m0 = w * 16 + g, m1 = m0 + 8;
    const int jlo0 = max((m0 >> 2) + 1, 128 - q0), jhi0 = (m0 >> 2) + 128;
    const int jlo1 = max((m1 >> 2) + 1, 128 - q0), jhi1 = (m1 >> 2) + 128;

    // warp-union valid key range (warp-uniform -> uniform branches)
    const int wjlo = max(4 * w + 1, 128 - q0);
    const int wjhi = 4 * w + 131;

    const int krow   = (lane & 7) + ((lane & 16) ? 8 : 0);
    const int kchoff = (lane & 8) ? 1 : 0;
    const int vrow   = (lane & 7) + ((lane & 8) ? 8 : 0);
    const int vchof  = (lane & 16) ? 1 : 0;

    float o[8][4];
#pragma unroll
    for (int nt = 0; nt < 8; ++nt)
#pragma unroll
        for (int e = 0; e < 4; ++e) o[nt][e] = 0.f;
    float mrun0 = -1e30f, mrun1 = -1e30f, sum0 = 0.f, sum1 = 0.f;

    const int cstart = (q0 == 0) ? 2 : 0;   // first block: chunks 0,1 fully masked
#pragma unroll 1
    for (int c = cstart; c < 3; ++c) {
        // ---- Q A-fragments for this warp (reloaded per chunk to cap regs) ----
        uint32_t qh[4][4], ql[4][4];
        {
            const int r  = w * 16 + (lane & 15);
            const int rx = r & 7;
#pragma unroll
            for (int kk = 0; kk < 4; ++kk) {
                const uint32_t chunk = (uint32_t)(kk * 2 + (lane >> 4));
                const uint32_t a = sb + SM_QHI + r * 128 + ((chunk ^ rx) << 4);
                ldsm4(qh[kk], a);
                ldsm4(ql[kk], a + (SM_QLO - SM_QHI));
            }
        }

        // ================= QK chunk: S[16,64], skipping masked tiles =========
        float s[8][4];
#pragma unroll
        for (int t = 0; t < 8; ++t)
#pragma unroll
            for (int e = 0; e < 4; ++e) s[t][e] = 0.f;

#pragma unroll
        for (int p = 0; p < 4; ++p) {
            const int jt = 64 * c + 16 * p;
            if (jt + 15 < wjlo || jt > wjhi) continue;   // fully-masked tile
#pragma unroll
            for (int kk = 0; kk < 4; ++kk) {
                const int r = jt + krow;
                const uint32_t chunk = (uint32_t)((kk * 2 + kchoff) ^ (r & 7));
                const uint32_t a = sb + SM_KHI + r * 128 + (chunk << 4);
                uint32_t kh[4], kl[4];
                ldsm4(kh, a);
                ldsm4(kl, a + (SM_KLO - SM_KHI));
                mma16816(s[2 * p],     qh[kk], kh[0], kh[1]);   // hi*hi
                mma16816(s[2 * p + 1], qh[kk], kh[2], kh[3]);
                mma16816(s[2 * p],     qh[kk], kl[0], kl[1]);   // hi*lo
                mma16816(s[2 * p + 1], qh[kk], kl[2], kl[3]);
                mma16816(s[2 * p],     ql[kk], kh[0], kh[1]);   // lo*hi
                mma16816(s[2 * p + 1], ql[kk], kh[2], kh[3]);
            }
        }

        // ================= mask + online softmax =================
        float cm0 = -1e30f, cm1 = -1e30f;
#pragma unroll
        for (int t = 0; t < 8; ++t)
#pragma unroll
            for (int e = 0; e < 2; ++e) {
                const int j = 64 * c + 8 * t + 2 * tg + e;
                s[t][e]     = (j >= jlo0 && j <= jhi0) ? s[t][e]     : -1e30f;
                s[t][2 + e] = (j >= jlo1 && j <= jhi1) ? s[t][2 + e] : -1e30f;
                cm0 = fmaxf(cm0, s[t][e]);
                cm1 = fmaxf(cm1, s[t][2 + e]);
            }
        cm0 = fmaxf(cm0, __shfl_xor_sync(0xffffffffu, cm0, 1));
        cm0 = fmaxf(cm0, __shfl_xor_sync(0xffffffffu, cm0, 2));
        cm1 = fmaxf(cm1, __shfl_xor_sync(0xffffffffu, cm1, 1));
        cm1 = fmaxf(cm1, __shfl_xor_sync(0xffffffffu, cm1, 2));

        const float mn0 = fmaxf(mrun0, cm0), mn1 = fmaxf(mrun1, cm1);
        const float corr0 = ex2(mrun0 - mn0), corr1 = ex2(mrun1 - mn1);
        mrun0 = mn0; mrun1 = mn1;

        uint32_t phi[4][4], plo[4][4];
        float cs0 = 0.f, cs1 = 0.f;
#pragma unroll
        for (int kk = 0; kk < 4; ++kk) {
            const int jt = 64 * c + 16 * kk;
            if (jt + 15 < wjlo || jt > wjhi) continue;   // P == 0 on this tile
            const float p00 = ex2(s[2 * kk][0] - mn0),     p01 = ex2(s[2 * kk][1] - mn0);
            const float p10 = ex2(s[2 * kk][2] - mn1),     p11 = ex2(s[2 * kk][3] - mn1);
            const float p02 = ex2(s[2 * kk + 1][0] - mn0), p03 = ex2(s[2 * kk + 1][1] - mn0);
            const float p12 = ex2(s[2 * kk + 1][2] - mn1), p13 = ex2(s[2 * kk + 1][3] - mn1);
            cs0 += (p00 + p01) + (p02 + p03);
            cs1 += (p10 + p11) + (p12 + p13);
            split2(p00, p01, phi[kk][0], plo[kk][0]);
            split2(p10, p11, phi[kk][1], plo[kk][1]);
            split2(p02, p03, phi[kk][2], plo[kk][2]);
            split2(p12, p13, phi[kk][3], plo[kk][3]);
        }
        cs0 += __shfl_xor_sync(0xffffffffu, cs0, 1);
        cs0 += __shfl_xor_sync(0xffffffffu, cs0, 2);
        cs1 += __shfl_xor_sync(0xffffffffu, cs1, 1);
        cs1 += __shfl_xor_sync(0xffffffffu, cs1, 2);
        sum0 = sum0 * corr0 + cs0;
        sum1 = sum1 * corr1 + cs1;

#pragma unroll
        for (int nt = 0; nt < 8; ++nt) {
            o[nt][0] *= corr0; o[nt][1] *= corr0;
            o[nt][2] *= corr1; o[nt][3] *= corr1;
        }

        // ================= PV chunk: O[16,64] += P V, same tile skip =========
#pragma unroll
        for (int kk = 0; kk < 4; ++kk) {
            const int jt = 64 * c + 16 * kk;
            if (jt + 15 < wjlo || jt > wjhi) continue;
#pragma unroll
            for (int np = 0; np < 4; ++np) {
                const int r = jt + vrow;
                const uint32_t chunk = (uint32_t)((np * 2 + vchof) ^ (r & 7));
                const uint32_t a = sb + SM_VHI + r * 128 + (chunk << 4);
                uint32_t vh[4], vl[4];
                ldsm4t(vh, a);
                ldsm4t(vl, a + (SM_VLO - SM_VHI));
                mma16816(o[2 * np],     phi[kk], vh[0], vh[1]);   // hi*hi
                mma16816(o[2 * np + 1], phi[kk], vh[2], vh[3]);
                mma16816(o[2 * np],     phi[kk], vl[0], vl[1]);   // hi*lo
                mma16816(o[2 * np + 1], phi[kk], vl[2], vl[3]);
                mma16816(o[2 * np],     plo[kk], vh[0], vh[1]);   // lo*hi
                mma16816(o[2 * np + 1], plo[kk], vh[2], vh[3]);
            }
        }
    }

    // ================= normalize + store =================
    const float inv0 = 1.f / sum0, inv1 = 1.f / sum1;
    float* ob0 = Og + ((size_t)(b * SEQ + q0 + (m0 >> 2)) * 32 + kvh * 4 + (m0 & 3)) * 64;
    float* ob1 = Og + ((size_t)(b * SEQ + q0 + (m1 >> 2)) * 32 + kvh * 4 + (m1 & 3)) * 64;
#pragma unroll
    for (int nt = 0; nt < 8; ++nt) {
        const int d = nt * 8 + 2 * tg;
        *reinterpret_cast<float2*>(ob0 + d) = make_float2(o[nt][0] * inv0, o[nt][1] * inv0);
        *reinterpret_cast<float2*>(ob1 + d) = make_float2(o[nt][2] * inv1, o[nt][3] * inv1);
    }
}

} // namespace

extern "C" void kernel_launch(void* const* d_in, const int* in_sizes, int n_in,
                              void* d_out, int out_size)
{
    (void)in_sizes; (void)n_in; (void)out_size;
    const float* Q = (const float*)d_in[0];
    const float* K = (const float*)d_in[1];
    const float* V = (const float*)d_in[2];
    // d_in[3] = sinks — unused by the reference math, faithfully ignored.
    float* O = (float*)d_out;

    cudaFuncSetAttribute(swa_mma_kernel, cudaFuncAttributeMaxDynamicSharedMemorySize,
                         SMEM_BYTES);

    dim3 grid(SEQ / 64, 8, 2);
    swa_mma_kernel<<<grid, 512, SMEM_BYTES>>>(Q, K, V, O);
}

// round 8
// speedup vs baseline: 1.4042x; 1.4042x over previous
#include <cuda_runtime.h>
#include <cuda_bf16.h>
#include <cstdint>
#include <math.h>

// Sliding-window causal GQA attention via mma.sync (HMMA) bf16 split-precision.
// B=2, S=2048, 8 kv heads x 4 q-heads/kv, D=64, WINDOW=128, fp32 in/out.
// CTA = (b, kvh, 32 queries): M=128 rows (32q x 4h), exact 160-key window,
// 8 warps, 2 CTAs/SM (K/V-only smem = 80KB; Q fragments built from global
// directly into registers, held across chunks). Keys in 5 branch-free chunks
// of 32 with online softmax. Split-bf16: x = hi + lo; 3-term mma ~2^-17.

namespace {

constexpr int SEQ = 2048;
constexpr float QSCALE = 0.125f * 1.4426950408889634f;  // 1/sqrt(64) * log2(e)

// smem byte offsets: rows of 128B (64 bf16), 16B-chunk XOR swizzle
constexpr int SM_KHI = 0;          // 160 x 128B
constexpr int SM_KLO = 20480;
constexpr int SM_VHI = 40960;
constexpr int SM_VLO = 61440;
constexpr int SMEM_BYTES = 81920;  // 80 KB -> 2 CTAs/SM

__device__ __forceinline__ uint32_t smem_u32(const void* p) {
    uint32_t a;
    asm("{ .reg .u64 t; cvta.to.shared.u64 t, %1; cvt.u32.u64 %0, t; }" : "=r"(a) : "l"(p));
    return a;
}
__device__ __forceinline__ void ldsm4(uint32_t r[4], uint32_t a) {
    asm volatile("ldmatrix.sync.aligned.m8n8.x4.shared.b16 {%0,%1,%2,%3}, [%4];"
                 : "=r"(r[0]), "=r"(r[1]), "=r"(r[2]), "=r"(r[3]) : "r"(a));
}
__device__ __forceinline__ void ldsm4t(uint32_t r[4], uint32_t a) {
    asm volatile("ldmatrix.sync.aligned.m8n8.x4.trans.shared.b16 {%0,%1,%2,%3}, [%4];"
                 : "=r"(r[0]), "=r"(r[1]), "=r"(r[2]), "=r"(r[3]) : "r"(a));
}
__device__ __forceinline__ void mma16816(float d[4], const uint32_t a[4],
                                         uint32_t b0, uint32_t b1) {
    asm volatile(
        "mma.sync.aligned.m16n8k16.row.col.f32.bf16.bf16.f32 "
        "{%0,%1,%2,%3}, {%4,%5,%6,%7}, {%8,%9}, {%0,%1,%2,%3};"
        : "+f"(d[0]), "+f"(d[1]), "+f"(d[2]), "+f"(d[3])
        : "r"(a[0]), "r"(a[1]), "r"(a[2]), "r"(a[3]), "r"(b0), "r"(b1));
}
__device__ __forceinline__ float ex2(float x) {
    float r; asm("ex2.approx.ftz.f32 %0, %1;" : "=f"(r) : "f"(x)); return r;
}
__device__ __forceinline__ void split2(float x, float y, uint32_t& hi, uint32_t& lo) {
    __nv_bfloat162 h = __floats2bfloat162_rn(x, y);
    hi = *reinterpret_cast<uint32_t*>(&h);
    __nv_bfloat162 l = __floats2bfloat162_rn(x - __bfloat162float(h.x),
                                             y - __bfloat162float(h.y));
    lo = *reinterpret_cast<uint32_t*>(&l);
}

__global__ void __launch_bounds__(256, 2)
swa_mma_kernel(const float* __restrict__ Qg,
               const float* __restrict__ Kg,
               const float* __restrict__ Vg,
               float* __restrict__ Og)
{
    extern __shared__ char smem[];
    const uint32_t sb = smem_u32(smem);

    const int tid  = threadIdx.x;
    const int lane = tid & 31;
    const int w    = tid >> 5;
    const int q0   = blockIdx.x * 32;
    const int kvh  = blockIdx.y;
    const int b    = blockIdx.z;

    const int g  = lane >> 2, tg = lane & 3;
    const int m0 = w * 16 + g, m1 = m0 + 8;

    // ---- Q A-fragments straight from global (scaled, split hi/lo) ----
    const float* qrow0 = Qg + ((size_t)(b * SEQ + q0 + (m0 >> 2)) * 32 + kvh * 4 + (m0 & 3)) * 64;
    const float* qrow1 = Qg + ((size_t)(b * SEQ + q0 + (m1 >> 2)) * 32 + kvh * 4 + (m1 & 3)) * 64;
    uint32_t qh[4][4], ql[4][4];
#pragma unroll
    for (int kk = 0; kk < 4; ++kk) {
        const int c0 = 16 * kk + 2 * tg;
        const float2 x0 = *reinterpret_cast<const float2*>(qrow0 + c0);
        const float2 x1 = *reinterpret_cast<const float2*>(qrow1 + c0);
        const float2 x2 = *reinterpret_cast<const float2*>(qrow0 + c0 + 8);
        const float2 x3 = *reinterpret_cast<const float2*>(qrow1 + c0 + 8);
        split2(x0.x * QSCALE, x0.y * QSCALE, qh[kk][0], ql[kk][0]);
        split2(x1.x * QSCALE, x1.y * QSCALE, qh[kk][1], ql[kk][1]);
        split2(x2.x * QSCALE, x2.y * QSCALE, qh[kk][2], ql[kk][2]);
        split2(x3.x * QSCALE, x3.y * QSCALE, qh[kk][3], ql[kk][3]);
    }

    // ---- stage K and V (160 key rows: q0-128 .. q0+31), zero-filled below 0 ----
    for (int i = tid; i < 160 * 16; i += 256) {
        const int r = i >> 4, c4 = i & 15;
        const int key = q0 - 128 + r;
        float4 kv = make_float4(0.f, 0.f, 0.f, 0.f), vv = kv;
        if (key >= 0) {
            const size_t gidx = ((size_t)(b * SEQ + key) * 8 + kvh) * 64 + c4 * 4;
            kv = *reinterpret_cast<const float4*>(Kg + gidx);
            vv = *reinterpret_cast<const float4*>(Vg + gidx);
        }
        const uint32_t off = r * 128 + ((((c4 >> 1) ^ (r & 7))) << 4) + ((c4 & 1) << 3);
        uint32_t h0, l0, h1, l1;
        split2(kv.x, kv.y, h0, l0); split2(kv.z, kv.w, h1, l1);
        *reinterpret_cast<uint2*>(smem + SM_KHI + off) = make_uint2(h0, h1);
        *reinterpret_cast<uint2*>(smem + SM_KLO + off) = make_uint2(l0, l1);
        split2(vv.x, vv.y, h0, l0); split2(vv.z, vv.w, h1, l1);
        *reinterpret_cast<uint2*>(smem + SM_VHI + off) = make_uint2(h0, h1);
        *reinterpret_cast<uint2*>(smem + SM_VLO + off) = make_uint2(l0, l1);
    }
    __syncthreads();

    const int jlo0 = max((m0 >> 2) + 1, 128 - q0), jhi0 = (m0 >> 2) + 128;
    const int jlo1 = max((m1 >> 2) + 1, 128 - q0), jhi1 = (m1 >> 2) + 128;

    const int krow   = (lane & 7) + ((lane & 16) ? 8 : 0);
    const int kchoff = (lane & 8) ? 1 : 0;
    const int vrow   = (lane & 7) + ((lane & 8) ? 8 : 0);
    const int vchof  = (lane & 16) ? 1 : 0;

    float o[8][4];
#pragma unroll
    for (int nt = 0; nt < 8; ++nt)
#pragma unroll
        for (int e = 0; e < 4; ++e) o[nt][e] = 0.f;
    float mrun0 = -1e30f, mrun1 = -1e30f, sum0 = 0.f, sum1 = 0.f;

    const int cstart = (q0 == 0) ? 4 : 0;   // first block: keys 0..127 fully masked
#pragma unroll 1
    for (int c = cstart; c < 5; ++c) {
        // ================= QK chunk: S[16,32] =================
        float s[4][4];
#pragma unroll
        for (int t = 0; t < 4; ++t)
#pragma unroll
            for (int e = 0; e < 4; ++e) s[t][e] = 0.f;

#pragma unroll
        for (int kk = 0; kk < 4; ++kk) {
#pragma unroll
            for (int p = 0; p < 2; ++p) {
                const int r = 32 * c + 16 * p + krow;
                const uint32_t chunk = (uint32_t)((kk * 2 + kchoff) ^ (r & 7));
                const uint32_t a = sb + SM_KHI + r * 128 + (chunk << 4);
                uint32_t kh[4], kl[4];
                ldsm4(kh, a);
                ldsm4(kl, a + (SM_KLO - SM_KHI));
                mma16816(s[2 * p],     qh[kk], kh[0], kh[1]);   // hi*hi
                mma16816(s[2 * p + 1], qh[kk], kh[2], kh[3]);
                mma16816(s[2 * p],     qh[kk], kl[0], kl[1]);   // hi*lo
                mma16816(s[2 * p + 1], qh[kk], kl[2], kl[3]);
                mma16816(s[2 * p],     ql[kk], kh[0], kh[1]);   // lo*hi
                mma16816(s[2 * p + 1], ql[kk], kh[2], kh[3]);
            }
        }

        // ================= mask + online softmax =================
        float cm0 = -1e30f, cm1 = -1e30f;
#pragma unroll
        for (int t = 0; t < 4; ++t)
#pragma unroll
            for (int e = 0; e < 2; ++e) {
                const int j = 32 * c + 8 * t + 2 * tg + e;
                s[t][e]     = (j >= jlo0 && j <= jhi0) ? s[t][e]     : -1e30f;
                s[t][2 + e] = (j >= jlo1 && j <= jhi1) ? s[t][2 + e] : -1e30f;
                cm0 = fmaxf(cm0, s[t][e]);
                cm1 = fmaxf(cm1, s[t][2 + e]);
            }
        cm0 = fmaxf(cm0, __shfl_xor_sync(0xffffffffu, cm0, 1));
        cm0 = fmaxf(cm0, __shfl_xor_sync(0xffffffffu, cm0, 2));
        cm1 = fmaxf(cm1, __shfl_xor_sync(0xffffffffu, cm1, 1));
        cm1 = fmaxf(cm1, __shfl_xor_sync(0xffffffffu, cm1, 2));

        const float mn0 = fmaxf(mrun0, cm0), mn1 = fmaxf(mrun1, cm1);
        const float corr0 = ex2(mrun0 - mn0), corr1 = ex2(mrun1 - mn1);
        mrun0 = mn0; mrun1 = mn1;

        uint32_t phi[2][4], plo[2][4];
        float cs0 = 0.f, cs1 = 0.f;
#pragma unroll
        for (int kk = 0; kk < 2; ++kk) {
            const float p00 = ex2(s[2 * kk][0] - mn0),     p01 = ex2(s[2 * kk][1] - mn0);
            const float p10 = ex2(s[2 * kk][2] - mn1),     p11 = ex2(s[2 * kk][3] - mn1);
            const float p02 = ex2(s[2 * kk + 1][0] - mn0), p03 = ex2(s[2 * kk + 1][1] - mn0);
            const float p12 = ex2(s[2 * kk + 1][2] - mn1), p13 = ex2(s[2 * kk + 1][3] - mn1);
            cs0 += (p00 + p01) + (p02 + p03);
            cs1 += (p10 + p11) + (p12 + p13);
            split2(p00, p01, phi[kk][0], plo[kk][0]);
            split2(p10, p11, phi[kk][1], plo[kk][1]);
            split2(p02, p03, phi[kk][2], plo[kk][2]);
            split2(p12, p13, phi[kk][3], plo[kk][3]);
        }
        cs0 += __shfl_xor_sync(0xffffffffu, cs0, 1);
        cs0 += __shfl_xor_sync(0xffffffffu, cs0, 2);
        cs1 += __shfl_xor_sync(0xffffffffu, cs1, 1);
        cs1 += __shfl_xor_sync(0xffffffffu, cs1, 2);
        sum0 = sum0 * corr0 + cs0;
        sum1 = sum1 * corr1 + cs1;

#pragma unroll
        for (int nt = 0; nt < 8; ++nt) {
            o[nt][0] *= corr0; o[nt][1] *= corr0;
            o[nt][2] *= corr1; o[nt][3] *= corr1;
        }

        // ================= PV chunk: O[16,64] += P V =================
#pragma unroll
        for (int kk = 0; kk < 2; ++kk) {
#pragma unroll
            for (int np = 0; np < 4; ++np) {
                const int r = 32 * c + 16 * kk + vrow;
                const uint32_t chunk = (uint32_t)((np * 2 + vchof) ^ (r & 7));
                const uint32_t a = sb + SM_VHI + r * 128 + (chunk << 4);
                uint32_t vh[4], vl[4];
                ldsm4t(vh, a);
                ldsm4t(vl, a + (SM_VLO - SM_VHI));
                mma16816(o[2 * np],     phi[kk], vh[0], vh[1]);   // hi*hi
                mma16816(o[2 * np + 1], phi[kk], vh[2], vh[3]);
                mma16816(o[2 * np],     phi[kk], vl[0], vl[1]);   // hi*lo
                mma16816(o[2 * np + 1], phi[kk], vl[2], vl[3]);
                mma16816(o[2 * np],     plo[kk], vh[0], vh[1]);   // lo*hi
                mma16816(o[2 * np + 1], plo[kk], vh[2], vh[3]);
            }
        }
    }

    // ================= normalize + store (O layout == Q layout) =================
    const float inv0 = 1.f / sum0, inv1 = 1.f / sum1;
    float* ob0 = Og + (qrow0 - Qg);
    float* ob1 = Og + (qrow1 - Qg);
#pragma unroll
    for (int nt = 0; nt < 8; ++nt) {
        const int d = nt * 8 + 2 * tg;
        *reinterpret_cast<float2*>(ob0 + d) = make_float2(o[nt][0] * inv0, o[nt][1] * inv0);
        *reinterpret_cast<float2*>(ob1 + d) = make_float2(o[nt][2] * inv1, o[nt][3] * inv1);
    }
}

} // namespace

extern "C" void kernel_launch(void* const* d_in, const int* in_sizes, int n_in,
                              void* d_out, int out_size)
{
    (void)in_sizes; (void)n_in; (void)out_size;
    const float* Q = (const float*)d_in[0];
    const float* K = (const float*)d_in[1];
    const float* V = (const float*)d_in[2];
    // d_in[3] = sinks — unused by the reference math, faithfully ignored.
    float* O = (float*)d_out;

    cudaFuncSetAttribute(swa_mma_kernel, cudaFuncAttributeMaxDynamicSharedMemorySize,
                         SMEM_BYTES);

    dim3 grid(SEQ / 32, 8, 2);
    swa_mma_kernel<<<grid, 256, SMEM_BYTES>>>(Q, K, V, O);
}

// round 9
// speedup vs baseline: 1.8178x; 1.2946x over previous
#include <cuda_runtime.h>
#include <cuda_fp16.h>
#include <cstdint>
#include <math.h>

// Sliding-window causal GQA attention via mma.sync (HMMA) fp16 asymmetric split.
// B=2, S=2048, 8 kv heads x 4 q-heads/kv, D=64, WINDOW=128, fp32 in/out.
// CTA = (b, kvh, 32 queries): M=128 rows (32q x 4h), exact 160-key window,
// 8 warps, 2 CTAs/SM (40KB smem). Keys in 5 branch-free chunks of 32, online
// softmax. Precision: Q and P are 2-term fp16 splits (exact to ~2^-22, kept in
// registers); K and V are 1-term fp16 (error ~2^-11 -> rel_err ~4e-4 < 1e-3).
// Q split unscaled (avoids fp16-subnormal residuals); scale*log2e applied to S.

namespace {

constexpr int SEQ = 2048;
constexpr float SSCALE = 0.125f * 1.4426950408889634f;  // 1/sqrt(64) * log2(e)

// smem byte offsets: rows of 128B (64 fp16), 16B-chunk XOR swizzle
constexpr int SM_KH = 0;           // 160 x 128B
constexpr int SM_VH = 20480;
constexpr int SMEM_BYTES = 40960;  // 40 KB -> 2 CTAs/SM

__device__ __forceinline__ uint32_t smem_u32(const void* p) {
    uint32_t a;
    asm("{ .reg .u64 t; cvta.to.shared.u64 t, %1; cvt.u32.u64 %0, t; }" : "=r"(a) : "l"(p));
    return a;
}
__device__ __forceinline__ void ldsm4(uint32_t r[4], uint32_t a) {
    asm volatile("ldmatrix.sync.aligned.m8n8.x4.shared.b16 {%0,%1,%2,%3}, [%4];"
                 : "=r"(r[0]), "=r"(r[1]), "=r"(r[2]), "=r"(r[3]) : "r"(a));
}
__device__ __forceinline__ void ldsm4t(uint32_t r[4], uint32_t a) {
    asm volatile("ldmatrix.sync.aligned.m8n8.x4.trans.shared.b16 {%0,%1,%2,%3}, [%4];"
                 : "=r"(r[0]), "=r"(r[1]), "=r"(r[2]), "=r"(r[3]) : "r"(a));
}
__device__ __forceinline__ void mma16816(float d[4], const uint32_t a[4],
                                         uint32_t b0, uint32_t b1) {
    asm volatile(
        "mma.sync.aligned.m16n8k16.row.col.f32.f16.f16.f32 "
        "{%0,%1,%2,%3}, {%4,%5,%6,%7}, {%8,%9}, {%0,%1,%2,%3};"
        : "+f"(d[0]), "+f"(d[1]), "+f"(d[2]), "+f"(d[3])
        : "r"(a[0]), "r"(a[1]), "r"(a[2]), "r"(a[3]), "r"(b0), "r"(b1));
}
__device__ __forceinline__ float ex2(float x) {
    float r; asm("ex2.approx.ftz.f32 %0, %1;" : "=f"(r) : "f"(x)); return r;
}
__device__ __forceinline__ uint32_t h2(float x, float y) {
    __half2 t = __floats2half2_rn(x, y);
    return *reinterpret_cast<uint32_t*>(&t);
}
__device__ __forceinline__ void split2h(float x, float y, uint32_t& hi, uint32_t& lo) {
    __half2 h = __floats2half2_rn(x, y);
    hi = *reinterpret_cast<uint32_t*>(&h);
    __half2 l = __floats2half2_rn(x - __low2float(h), y - __high2float(h));
    lo = *reinterpret_cast<uint32_t*>(&l);
}

__global__ void __launch_bounds__(256, 2)
swa_mma_kernel(const float* __restrict__ Qg,
               const float* __restrict__ Kg,
               const float* __restrict__ Vg,
               float* __restrict__ Og)
{
    extern __shared__ char smem[];
    const uint32_t sb = smem_u32(smem);

    const int tid  = threadIdx.x;
    const int lane = tid & 31;
    const int w    = tid >> 5;
    const int q0   = blockIdx.x * 32;
    const int kvh  = blockIdx.y;
    const int b    = blockIdx.z;

    const int g  = lane >> 2, tg = lane & 3;
    const int m0 = w * 16 + g, m1 = m0 + 8;

    // ---- Q A-fragments straight from global (UNSCALED, 2-term fp16 split) ----
    const float* qrow0 = Qg + ((size_t)(b * SEQ + q0 + (m0 >> 2)) * 32 + kvh * 4 + (m0 & 3)) * 64;
    const float* qrow1 = Qg + ((size_t)(b * SEQ + q0 + (m1 >> 2)) * 32 + kvh * 4 + (m1 & 3)) * 64;
    uint32_t qh[4][4], ql[4][4];
#pragma unroll
    for (int kk = 0; kk < 4; ++kk) {
        const int c0 = 16 * kk + 2 * tg;
        const float2 x0 = *reinterpret_cast<const float2*>(qrow0 + c0);
        const float2 x1 = *reinterpret_cast<const float2*>(qrow1 + c0);
        const float2 x2 = *reinterpret_cast<const float2*>(qrow0 + c0 + 8);
        const float2 x3 = *reinterpret_cast<const float2*>(qrow1 + c0 + 8);
        split2h(x0.x, x0.y, qh[kk][0], ql[kk][0]);
        split2h(x1.x, x1.y, qh[kk][1], ql[kk][1]);
        split2h(x2.x, x2.y, qh[kk][2], ql[kk][2]);
        split2h(x3.x, x3.y, qh[kk][3], ql[kk][3]);
    }

    // ---- stage K and V as 1-term fp16 (160 key rows: q0-128 .. q0+31) ----
    for (int i = tid; i < 160 * 16; i += 256) {
        const int r = i >> 4, c4 = i & 15;
        const int key = q0 - 128 + r;
        float4 kv = make_float4(0.f, 0.f, 0.f, 0.f), vv = kv;
        if (key >= 0) {
            const size_t gidx = ((size_t)(b * SEQ + key) * 8 + kvh) * 64 + c4 * 4;
            kv = *reinterpret_cast<const float4*>(Kg + gidx);
            vv = *reinterpret_cast<const float4*>(Vg + gidx);
        }
        const uint32_t off = r * 128 + ((((c4 >> 1) ^ (r & 7))) << 4) + ((c4 & 1) << 3);
        *reinterpret_cast<uint2*>(smem + SM_KH + off) = make_uint2(h2(kv.x, kv.y), h2(kv.z, kv.w));
        *reinterpret_cast<uint2*>(smem + SM_VH + off) = make_uint2(h2(vv.x, vv.y), h2(vv.z, vv.w));
    }
    __syncthreads();

    const int jlo0 = max((m0 >> 2) + 1, 128 - q0), jhi0 = (m0 >> 2) + 128;
    const int jlo1 = max((m1 >> 2) + 1, 128 - q0), jhi1 = (m1 >> 2) + 128;

    const int krow   = (lane & 7) + ((lane & 16) ? 8 : 0);
    const int kchoff = (lane & 8) ? 1 : 0;
    const int vrow   = (lane & 7) + ((lane & 8) ? 8 : 0);
    const int vchof  = (lane & 16) ? 1 : 0;

    float o[8][4];
#pragma unroll
    for (int nt = 0; nt < 8; ++nt)
#pragma unroll
        for (int e = 0; e < 4; ++e) o[nt][e] = 0.f;
    float mrun0 = -1e30f, mrun1 = -1e30f, sum0 = 0.f, sum1 = 0.f;

    const int cstart = (q0 == 0) ? 4 : 0;   // first block: keys 0..127 fully masked
#pragma unroll 1
    for (int c = cstart; c < 5; ++c) {
        // ================= QK chunk: S[16,32] =================
        float s[4][4];
#pragma unroll
        for (int t = 0; t < 4; ++t)
#pragma unroll
            for (int e = 0; e < 4; ++e) s[t][e] = 0.f;

#pragma unroll
        for (int kk = 0; kk < 4; ++kk) {
#pragma unroll
            for (int p = 0; p < 2; ++p) {
                const int r = 32 * c + 16 * p + krow;
                const uint32_t chunk = (uint32_t)((kk * 2 + kchoff) ^ (r & 7));
                const uint32_t a = sb + SM_KH + r * 128 + (chunk << 4);
                uint32_t kh[4];
                ldsm4(kh, a);
                mma16816(s[2 * p],     qh[kk], kh[0], kh[1]);   // q_hi * k
                mma16816(s[2 * p + 1], qh[kk], kh[2], kh[3]);
                mma16816(s[2 * p],     ql[kk], kh[0], kh[1]);   // q_lo * k
                mma16816(s[2 * p + 1], ql[kk], kh[2], kh[3]);
            }
        }

        // ================= scale + mask + online softmax =================
        float cm0 = -1e30f, cm1 = -1e30f;
#pragma unroll
        for (int t = 0; t < 4; ++t)
#pragma unroll
            for (int e = 0; e < 2; ++e) {
                const int j = 32 * c + 8 * t + 2 * tg + e;
                const float v0 = s[t][e] * SSCALE;
                const float v1 = s[t][2 + e] * SSCALE;
                s[t][e]     = (j >= jlo0 && j <= jhi0) ? v0 : -1e30f;
                s[t][2 + e] = (j >= jlo1 && j <= jhi1) ? v1 : -1e30f;
                cm0 = fmaxf(cm0, s[t][e]);
                cm1 = fmaxf(cm1, s[t][2 + e]);
            }
        cm0 = fmaxf(cm0, __shfl_xor_sync(0xffffffffu, cm0, 1));
        cm0 = fmaxf(cm0, __shfl_xor_sync(0xffffffffu, cm0, 2));
        cm1 = fmaxf(cm1, __shfl_xor_sync(0xffffffffu, cm1, 1));
        cm1 = fmaxf(cm1, __shfl_xor_sync(0xffffffffu, cm1, 2));

        const float mn0 = fmaxf(mrun0, cm0), mn1 = fmaxf(mrun1, cm1);
        const float corr0 = ex2(mrun0 - mn0), corr1 = ex2(mrun1 - mn1);
        mrun0 = mn0; mrun1 = mn1;

        uint32_t phi[2][4], plo[2][4];
        float cs0 = 0.f, cs1 = 0.f;
#pragma unroll
        for (int kk = 0; kk < 2; ++kk) {
            const float p00 = ex2(s[2 * kk][0] - mn0),     p01 = ex2(s[2 * kk][1] - mn0);
            const float p10 = ex2(s[2 * kk][2] - mn1),     p11 = ex2(s[2 * kk][3] - mn1);
            const float p02 = ex2(s[2 * kk + 1][0] - mn0), p03 = ex2(s[2 * kk + 1][1] - mn0);
            const float p12 = ex2(s[2 * kk + 1][2] - mn1), p13 = ex2(s[2 * kk + 1][3] - mn1);
            cs0 += (p00 + p01) + (p02 + p03);
            cs1 += (p10 + p11) + (p12 + p13);
            split2h(p00, p01, phi[kk][0], plo[kk][0]);
            split2h(p10, p11, phi[kk][1], plo[kk][1]);
            split2h(p02, p03, phi[kk][2], plo[kk][2]);
            split2h(p12, p13, phi[kk][3], plo[kk][3]);
        }
        cs0 += __shfl_xor_sync(0xffffffffu, cs0, 1);
        cs0 += __shfl_xor_sync(0xffffffffu, cs0, 2);
        cs1 += __shfl_xor_sync(0xffffffffu, cs1, 1);
        cs1 += __shfl_xor_sync(0xffffffffu, cs1, 2);
        sum0 = sum0 * corr0 + cs0;
        sum1 = sum1 * corr1 + cs1;

#pragma unroll
        for (int nt = 0; nt < 8; ++nt) {
            o[nt][0] *= corr0; o[nt][1] *= corr0;
            o[nt][2] *= corr1; o[nt][3] *= corr1;
        }

        // ================= PV chunk: O[16,64] += P V =================
#pragma unroll
        for (int kk = 0; kk < 2; ++kk) {
#pragma unroll
            for (int np = 0; np < 4; ++np) {
                const int r = 32 * c + 16 * kk + vrow;
                const uint32_t chunk = (uint32_t)((np * 2 + vchof) ^ (r & 7));
                const uint32_t a = sb + SM_VH + r * 128 + (chunk << 4);
                uint32_t vh[4];
                ldsm4t(vh, a);
                mma16816(o[2 * np],     phi[kk], vh[0], vh[1]);   // p_hi * v
                mma16816(o[2 * np + 1], phi[kk], vh[2], vh[3]);
                mma16816(o[2 * np],     plo[kk], vh[0], vh[1]);   // p_lo * v
                mma16816(o[2 * np + 1], plo[kk], vh[2], vh[3]);
            }
        }
    }

    // ================= normalize + store (O layout == Q layout) =================
    const float inv0 = 1.f / sum0, inv1 = 1.f / sum1;
    float* ob0 = Og + (qrow0 - Qg);
    float* ob1 = Og + (qrow1 - Qg);
#pragma unroll
    for (int nt = 0; nt < 8; ++nt) {
        const int d = nt * 8 + 2 * tg;
        *reinterpret_cast<float2*>(ob0 + d) = make_float2(o[nt][0] * inv0, o[nt][1] * inv0);
        *reinterpret_cast<float2*>(ob1 + d) = make_float2(o[nt][2] * inv1, o[nt][3] * inv1);
    }
}

} // namespace

extern "C" void kernel_launch(void* const* d_in, const int* in_sizes, int n_in,
                              void* d_out, int out_size)
{
    (void)in_sizes; (void)n_in; (void)out_size;
    const float* Q = (const float*)d_in[0];
    const float* K = (const float*)d_in[1];
    const float* V = (const float*)d_in[2];
    // d_in[3] = sinks — unused by the reference math, faithfully ignored.
    float* O = (float*)d_out;

    cudaFuncSetAttribute(swa_mma_kernel, cudaFuncAttributeMaxDynamicSharedMemorySize,
                         SMEM_BYTES);

    dim3 grid(SEQ / 32, 8, 2);
    swa_mma_kernel<<<grid, 256, SMEM_BYTES>>>(Q, K, V, O);
}

// round 10
// speedup vs baseline: 1.9170x; 1.0546x over previous
#include <cuda_runtime.h>
#include <cuda_fp16.h>
#include <cstdint>
#include <math.h>

// Sliding-window causal GQA attention via mma.sync (HMMA) fp16 asymmetric split.
// B=2, S=2048, 8 kv heads x 4 q-heads/kv, D=64, WINDOW=128, fp32 in/out.
// CTA = (b, kvh, 32 queries): M=128 rows (32q x 4h), exact 160-key window,
// 8 warps, 2 CTAs/SM (40KB smem). Keys in 5 branch-free chunks of 32, online
// softmax. Precision: Q = 2-term fp16 split (held in regs, exact to ~2^-22);
// K, V, P = 1-term fp16 (rel_err ~4e-4 < 1e-3). Q split unscaled; scale*log2e
// applied to S. LDSMs grouped ahead of MMA bursts; swizzle bases hoisted.

namespace {

constexpr int SEQ = 2048;
constexpr float SSCALE = 0.125f * 1.4426950408889634f;  // 1/sqrt(64) * log2(e)

// smem byte offsets: rows of 128B (64 fp16), 16B-chunk XOR swizzle
constexpr int SM_KH = 0;           // 160 x 128B
constexpr int SM_VH = 20480;
constexpr int SMEM_BYTES = 40960;  // 40 KB -> 2 CTAs/SM

__device__ __forceinline__ uint32_t smem_u32(const void* p) {
    uint32_t a;
    asm("{ .reg .u64 t; cvta.to.shared.u64 t, %1; cvt.u32.u64 %0, t; }" : "=r"(a) : "l"(p));
    return a;
}
__device__ __forceinline__ void ldsm4(uint32_t r[4], uint32_t a) {
    asm volatile("ldmatrix.sync.aligned.m8n8.x4.shared.b16 {%0,%1,%2,%3}, [%4];"
                 : "=r"(r[0]), "=r"(r[1]), "=r"(r[2]), "=r"(r[3]) : "r"(a));
}
__device__ __forceinline__ void ldsm4t(uint32_t r[4], uint32_t a) {
    asm volatile("ldmatrix.sync.aligned.m8n8.x4.trans.shared.b16 {%0,%1,%2,%3}, [%4];"
                 : "=r"(r[0]), "=r"(r[1]), "=r"(r[2]), "=r"(r[3]) : "r"(a));
}
__device__ __forceinline__ void mma16816(float d[4], const uint32_t a[4],
                                         uint32_t b0, uint32_t b1) {
    asm volatile(
        "mma.sync.aligned.m16n8k16.row.col.f32.f16.f16.f32 "
        "{%0,%1,%2,%3}, {%4,%5,%6,%7}, {%8,%9}, {%0,%1,%2,%3};"
        : "+f"(d[0]), "+f"(d[1]), "+f"(d[2]), "+f"(d[3])
        : "r"(a[0]), "r"(a[1]), "r"(a[2]), "r"(a[3]), "r"(b0), "r"(b1));
}
__device__ __forceinline__ float ex2(float x) {
    float r; asm("ex2.approx.ftz.f32 %0, %1;" : "=f"(r) : "f"(x)); return r;
}
__device__ __forceinline__ uint32_t h2(float x, float y) {
    __half2 t = __floats2half2_rn(x, y);
    return *reinterpret_cast<uint32_t*>(&t);
}
__device__ __forceinline__ void split2h(float x, float y, uint32_t& hi, uint32_t& lo) {
    __half2 h = __floats2half2_rn(x, y);
    hi = *reinterpret_cast<uint32_t*>(&h);
    __half2 l = __floats2half2_rn(x - __low2float(h), y - __high2float(h));
    lo = *reinterpret_cast<uint32_t*>(&l);
}

__global__ void __launch_bounds__(256, 2)
swa_mma_kernel(const float* __restrict__ Qg,
               const float* __restrict__ Kg,
               const float* __restrict__ Vg,
               float* __restrict__ Og)
{
    extern __shared__ char smem[];
    const uint32_t sb = smem_u32(smem);

    const int tid  = threadIdx.x;
    const int lane = tid & 31;
    const int w    = tid >> 5;
    const int q0   = blockIdx.x * 32;
    const int kvh  = blockIdx.y;
    const int b    = blockIdx.z;

    const int g  = lane >> 2, tg = lane & 3;
    const int m0 = w * 16 + g, m1 = m0 + 8;

    // ---- Q A-fragments straight from global (UNSCALED, 2-term fp16 split) ----
    const float* qrow0 = Qg + ((size_t)(b * SEQ + q0 + (m0 >> 2)) * 32 + kvh * 4 + (m0 & 3)) * 64;
    const float* qrow1 = Qg + ((size_t)(b * SEQ + q0 + (m1 >> 2)) * 32 + kvh * 4 + (m1 & 3)) * 64;
    uint32_t qh[4][4], ql[4][4];
#pragma unroll
    for (int kk = 0; kk < 4; ++kk) {
        const int c0 = 16 * kk + 2 * tg;
        const float2 x0 = *reinterpret_cast<const float2*>(qrow0 + c0);
        const float2 x1 = *reinterpret_cast<const float2*>(qrow1 + c0);
        const float2 x2 = *reinterpret_cast<const float2*>(qrow0 + c0 + 8);
        const float2 x3 = *reinterpret_cast<const float2*>(qrow1 + c0 + 8);
        split2h(x0.x, x0.y, qh[kk][0], ql[kk][0]);
        split2h(x1.x, x1.y, qh[kk][1], ql[kk][1]);
        split2h(x2.x, x2.y, qh[kk][2], ql[kk][2]);
        split2h(x3.x, x3.y, qh[kk][3], ql[kk][3]);
    }

    // ---- stage K and V as 1-term fp16 (160 key rows: q0-128 .. q0+31) ----
    for (int i = tid; i < 160 * 16; i += 256) {
        const int r = i >> 4, c4 = i & 15;
        const int key = q0 - 128 + r;
        float4 kv = make_float4(0.f, 0.f, 0.f, 0.f), vv = kv;
        if (key >= 0) {
            const size_t gidx = ((size_t)(b * SEQ + key) * 8 + kvh) * 64 + c4 * 4;
            kv = *reinterpret_cast<const float4*>(Kg + gidx);
            vv = *reinterpret_cast<const float4*>(Vg + gidx);
        }
        const uint32_t off = r * 128 + ((((c4 >> 1) ^ (r & 7))) << 4) + ((c4 & 1) << 3);
        *reinterpret_cast<uint2*>(smem + SM_KH + off) = make_uint2(h2(kv.x, kv.y), h2(kv.z, kv.w));
        *reinterpret_cast<uint2*>(smem + SM_VH + off) = make_uint2(h2(vv.x, vv.y), h2(vv.z, vv.w));
    }
    __syncthreads();

    const int jlo0 = max((m0 >> 2) + 1, 128 - q0), jhi0 = (m0 >> 2) + 128;
    const int jlo1 = max((m1 >> 2) + 1, 128 - q0), jhi1 = (m1 >> 2) + 128;

    // hoisted LDSM base addresses (swizzle selector is chunk-invariant:
    // 32c + 16p == 0 mod 8, so row&7 == krow&7 / vrow&7)
    const int krow   = (lane & 7) + ((lane & 16) ? 8 : 0);
    const int kchoff = (lane & 8) ? 1 : 0;
    const int vrow   = (lane & 7) + ((lane & 8) ? 8 : 0);
    const int vchof  = (lane & 16) ? 1 : 0;
    uint32_t akk[4], avn[4];
#pragma unroll
    for (int kk = 0; kk < 4; ++kk)
        akk[kk] = sb + SM_KH + krow * 128 + ((uint32_t)((kk * 2 + kchoff) ^ (krow & 7)) << 4);
#pragma unroll
    for (int np = 0; np < 4; ++np)
        avn[np] = sb + SM_VH + vrow * 128 + ((uint32_t)((np * 2 + vchof) ^ (vrow & 7)) << 4);

    float o[8][4];
#pragma unroll
    for (int nt = 0; nt < 8; ++nt)
#pragma unroll
        for (int e = 0; e < 4; ++e) o[nt][e] = 0.f;
    float mrun0 = -1e30f, mrun1 = -1e30f, sum0 = 0.f, sum1 = 0.f;

    const int cstart = (q0 == 0) ? 4 : 0;   // first block: keys 0..127 fully masked
#pragma unroll 1
    for (int c = cstart; c < 5; ++c) {
        const uint32_t coff = (uint32_t)c * 4096;

        // ================= QK chunk: S[16,32] =================
        float s[4][4];
#pragma unroll
        for (int t = 0; t < 4; ++t)
#pragma unroll
            for (int e = 0; e < 4; ++e) s[t][e] = 0.f;

#pragma unroll
        for (int kk = 0; kk < 4; ++kk) {
            uint32_t k0[4], k1[4];
            ldsm4(k0, akk[kk] + coff);
            ldsm4(k1, akk[kk] + coff + 2048);
            mma16816(s[0], qh[kk], k0[0], k0[1]);
            mma16816(s[1], qh[kk], k0[2], k0[3]);
            mma16816(s[0], ql[kk], k0[0], k0[1]);
            mma16816(s[1], ql[kk], k0[2], k0[3]);
            mma16816(s[2], qh[kk], k1[0], k1[1]);
            mma16816(s[3], qh[kk], k1[2], k1[3]);
            mma16816(s[2], ql[kk], k1[0], k1[1]);
            mma16816(s[3], ql[kk], k1[2], k1[3]);
        }

        // ================= scale + mask + online softmax =================
        float cm0 = -1e30f, cm1 = -1e30f;
#pragma unroll
        for (int t = 0; t < 4; ++t)
#pragma unroll
            for (int e = 0; e < 2; ++e) {
                const int j = 32 * c + 8 * t + 2 * tg + e;
                const float v0 = s[t][e] * SSCALE;
                const float v1 = s[t][2 + e] * SSCALE;
                s[t][e]     = (j >= jlo0 && j <= jhi0) ? v0 : -1e30f;
                s[t][2 + e] = (j >= jlo1 && j <= jhi1) ? v1 : -1e30f;
                cm0 = fmaxf(cm0, s[t][e]);
                cm1 = fmaxf(cm1, s[t][2 + e]);
            }
        cm0 = fmaxf(cm0, __shfl_xor_sync(0xffffffffu, cm0, 1));
        cm0 = fmaxf(cm0, __shfl_xor_sync(0xffffffffu, cm0, 2));
        cm1 = fmaxf(cm1, __shfl_xor_sync(0xffffffffu, cm1, 1));
        cm1 = fmaxf(cm1, __shfl_xor_sync(0xffffffffu, cm1, 2));

        const float mn0 = fmaxf(mrun0, cm0), mn1 = fmaxf(mrun1, cm1);
        const float corr0 = ex2(mrun0 - mn0), corr1 = ex2(mrun1 - mn1);
        mrun0 = mn0; mrun1 = mn1;

        uint32_t phi[2][4];
        float cs0 = 0.f, cs1 = 0.f;
#pragma unroll
        for (int kk = 0; kk < 2; ++kk) {
            const float p00 = ex2(s[2 * kk][0] - mn0),     p01 = ex2(s[2 * kk][1] - mn0);
            const float p10 = ex2(s[2 * kk][2] - mn1),     p11 = ex2(s[2 * kk][3] - mn1);
            const float p02 = ex2(s[2 * kk + 1][0] - mn0), p03 = ex2(s[2 * kk + 1][1] - mn0);
            const float p12 = ex2(s[2 * kk + 1][2] - mn1), p13 = ex2(s[2 * kk + 1][3] - mn1);
            cs0 += (p00 + p01) + (p02 + p03);
            cs1 += (p10 + p11) + (p12 + p13);
            phi[kk][0] = h2(p00, p01);
            phi[kk][1] = h2(p10, p11);
            phi[kk][2] = h2(p02, p03);
            phi[kk][3] = h2(p12, p13);
        }
        cs0 += __shfl_xor_sync(0xffffffffu, cs0, 1);
        cs0 += __shfl_xor_sync(0xffffffffu, cs0, 2);
        cs1 += __shfl_xor_sync(0xffffffffu, cs1, 1);
        cs1 += __shfl_xor_sync(0xffffffffu, cs1, 2);
        sum0 = sum0 * corr0 + cs0;
        sum1 = sum1 * corr1 + cs1;

#pragma unroll
        for (int nt = 0; nt < 8; ++nt) {
            o[nt][0] *= corr0; o[nt][1] *= corr0;
            o[nt][2] *= corr1; o[nt][3] *= corr1;
        }

        // ================= PV chunk: O[16,64] += P V =================
#pragma unroll
        for (int kk = 0; kk < 2; ++kk) {
            uint32_t vh[4][4];
            ldsm4t(vh[0], avn[0] + coff + (uint32_t)kk * 2048);
            ldsm4t(vh[1], avn[1] + coff + (uint32_t)kk * 2048);
            ldsm4t(vh[2], avn[2] + coff + (uint32_t)kk * 2048);
            ldsm4t(vh[3], avn[3] + coff + (uint32_t)kk * 2048);
#pragma unroll
            for (int np = 0; np < 4; ++np) {
                mma16816(o[2 * np],     phi[kk], vh[np][0], vh[np][1]);
                mma16816(o[2 * np + 1], phi[kk], vh[np][2], vh[np][3]);
            }
        }
    }

    // ================= normalize + store (O layout == Q layout) =================
    const float inv0 = 1.f / sum0, inv1 = 1.f / sum1;
    float* ob0 = Og + (qrow0 - Qg);
    float* ob1 = Og + (qrow1 - Qg);
#pragma unroll
    for (int nt = 0; nt < 8; ++nt) {
        const int d = nt * 8 + 2 * tg;
        *reinterpret_cast<float2*>(ob0 + d) = make_float2(o[nt][0] * inv0, o[nt][1] * inv0);
        *reinterpret_cast<float2*>(ob1 + d) = make_float2(o[nt][2] * inv1, o[nt][3] * inv1);
    }
}

} // namespace

extern "C" void kernel_launch(void* const* d_in, const int* in_sizes, int n_in,
                              void* d_out, int out_size)
{
    (void)in_sizes; (void)n_in; (void)out_size;
    const float* Q = (const float*)d_in[0];
    const float* K = (const float*)d_in[1];
    const float* V = (const float*)d_in[2];
    // d_in[3] = sinks — unused by the reference math, faithfully ignored.
    float* O = (float*)d_out;

    cudaFuncSetAttribute(swa_mma_kernel, cudaFuncAttributeMaxDynamicSharedMemorySize,
                         SMEM_BYTES);

    dim3 grid(SEQ / 32, 8, 2);
    swa_mma_kernel<<<grid, 256, SMEM_BYTES>>>(Q, K, V, O);
}

// round 11
// speedup vs baseline: 2.1351x; 1.1137x over previous
#include <cuda_runtime.h>
#include <cuda_fp16.h>
#include <cstdint>
#include <math.h>

// Sliding-window causal GQA attention via mma.sync (HMMA), fp16 operands.
// B=2, S=2048, 8 kv heads x 4 q-heads/kv, D=64, WINDOW=128, fp32 in/out.
// CTA = (b, kvh, 32 queries): M=128 rows (32q x 4h), exact 160-key window,
// 8 warps, 2 CTAs/SM (40KB smem). Keys in 5 branch-free chunks of 32, online
// softmax. Precision: Q,K,V,P all 1-term fp16 (scale folded into Q);
// expected rel_err ~5e-4 < 1e-3. V tiles prefetched ahead of the softmax
// epilogue so LDSM latency overlaps the shuffle/ex2 chain; MMA asm is
// non-volatile so ptxas can schedule it into LDSM shadows.

namespace {

constexpr int SEQ = 2048;
constexpr float SSCALE = 0.125f * 1.4426950408889634f;  // 1/sqrt(64) * log2(e)

// smem byte offsets: rows of 128B (64 fp16), 16B-chunk XOR swizzle
constexpr int SM_KH = 0;           // 160 x 128B
constexpr int SM_VH = 20480;
constexpr int SMEM_BYTES = 40960;  // 40 KB -> 2 CTAs/SM

__device__ __forceinline__ uint32_t smem_u32(const void* p) {
    uint32_t a;
    asm("{ .reg .u64 t; cvta.to.shared.u64 t, %1; cvt.u32.u64 %0, t; }" : "=r"(a) : "l"(p));
    return a;
}
__device__ __forceinline__ void ldsm4(uint32_t r[4], uint32_t a) {
    asm volatile("ldmatrix.sync.aligned.m8n8.x4.shared.b16 {%0,%1,%2,%3}, [%4];"
                 : "=r"(r[0]), "=r"(r[1]), "=r"(r[2]), "=r"(r[3]) : "r"(a));
}
__device__ __forceinline__ void ldsm4t(uint32_t r[4], uint32_t a) {
    asm volatile("ldmatrix.sync.aligned.m8n8.x4.trans.shared.b16 {%0,%1,%2,%3}, [%4];"
                 : "=r"(r[0]), "=r"(r[1]), "=r"(r[2]), "=r"(r[3]) : "r"(a));
}
// NOTE: non-volatile — pure register op; lets ptxas schedule into LDSM shadows.
__device__ __forceinline__ void mma16816(float d[4], const uint32_t a[4],
                                         uint32_t b0, uint32_t b1) {
    asm("mma.sync.aligned.m16n8k16.row.col.f32.f16.f16.f32 "
        "{%0,%1,%2,%3}, {%4,%5,%6,%7}, {%8,%9}, {%0,%1,%2,%3};"
        : "+f"(d[0]), "+f"(d[1]), "+f"(d[2]), "+f"(d[3])
        : "r"(a[0]), "r"(a[1]), "r"(a[2]), "r"(a[3]), "r"(b0), "r"(b1));
}
__device__ __forceinline__ float ex2(float x) {
    float r; asm("ex2.approx.ftz.f32 %0, %1;" : "=f"(r) : "f"(x)); return r;
}
__device__ __forceinline__ uint32_t h2(float x, float y) {
    __half2 t = __floats2half2_rn(x, y);
    return *reinterpret_cast<uint32_t*>(&t);
}

__global__ void __launch_bounds__(256, 2)
swa_mma_kernel(const float* __restrict__ Qg,
               const float* __restrict__ Kg,
               const float* __restrict__ Vg,
               float* __restrict__ Og)
{
    extern __shared__ char smem[];
    const uint32_t sb = smem_u32(smem);

    const int tid  = threadIdx.x;
    const int lane = tid & 31;
    const int w    = tid >> 5;
    const int q0   = blockIdx.x * 32;
    const int kvh  = blockIdx.y;
    const int b    = blockIdx.z;

    const int g  = lane >> 2, tg = lane & 3;
    const int m0 = w * 16 + g, m1 = m0 + 8;

    // ---- Q A-fragments straight from global (scale*log2e folded in) ----
    const float* qrow0 = Qg + ((size_t)(b * SEQ + q0 + (m0 >> 2)) * 32 + kvh * 4 + (m0 & 3)) * 64;
    const float* qrow1 = Qg + ((size_t)(b * SEQ + q0 + (m1 >> 2)) * 32 + kvh * 4 + (m1 & 3)) * 64;
    uint32_t qh[4][4];
#pragma unroll
    for (int kk = 0; kk < 4; ++kk) {
        const int c0 = 16 * kk + 2 * tg;
        const float2 x0 = *reinterpret_cast<const float2*>(qrow0 + c0);
        const float2 x1 = *reinterpret_cast<const float2*>(qrow1 + c0);
        const float2 x2 = *reinterpret_cast<const float2*>(qrow0 + c0 + 8);
        const float2 x3 = *reinterpret_cast<const float2*>(qrow1 + c0 + 8);
        qh[kk][0] = h2(x0.x * SSCALE, x0.y * SSCALE);
        qh[kk][1] = h2(x1.x * SSCALE, x1.y * SSCALE);
        qh[kk][2] = h2(x2.x * SSCALE, x2.y * SSCALE);
        qh[kk][3] = h2(x3.x * SSCALE, x3.y * SSCALE);
    }

    // ---- stage K and V as fp16 (160 key rows: q0-128 .. q0+31) ----
    for (int i = tid; i < 160 * 16; i += 256) {
        const int r = i >> 4, c4 = i & 15;
        const int key = q0 - 128 + r;
        float4 kv = make_float4(0.f, 0.f, 0.f, 0.f), vv = kv;
        if (key >= 0) {
            const size_t gidx = ((size_t)(b * SEQ + key) * 8 + kvh) * 64 + c4 * 4;
            kv = *reinterpret_cast<const float4*>(Kg + gidx);
            vv = *reinterpret_cast<const float4*>(Vg + gidx);
        }
        const uint32_t off = r * 128 + ((((c4 >> 1) ^ (r & 7))) << 4) + ((c4 & 1) << 3);
        *reinterpret_cast<uint2*>(smem + SM_KH + off) = make_uint2(h2(kv.x, kv.y), h2(kv.z, kv.w));
        *reinterpret_cast<uint2*>(smem + SM_VH + off) = make_uint2(h2(vv.x, vv.y), h2(vv.z, vv.w));
    }
    __syncthreads();

    const int jlo0 = max((m0 >> 2) + 1, 128 - q0), jhi0 = (m0 >> 2) + 128;
    const int jlo1 = max((m1 >> 2) + 1, 128 - q0), jhi1 = (m1 >> 2) + 128;

    // hoisted LDSM base addresses (swizzle selector is chunk-invariant)
    const int krow   = (lane & 7) + ((lane & 16) ? 8 : 0);
    const int kchoff = (lane & 8) ? 1 : 0;
    const int vrow   = (lane & 7) + ((lane & 8) ? 8 : 0);
    const int vchof  = (lane & 16) ? 1 : 0;
    uint32_t akk[4], avn[4];
#pragma unroll
    for (int kk = 0; kk < 4; ++kk)
        akk[kk] = sb + SM_KH + krow * 128 + ((uint32_t)((kk * 2 + kchoff) ^ (krow & 7)) << 4);
#pragma unroll
    for (int np = 0; np < 4; ++np)
        avn[np] = sb + SM_VH + vrow * 128 + ((uint32_t)((np * 2 + vchof) ^ (vrow & 7)) << 4);

    float o[8][4];
#pragma unroll
    for (int nt = 0; nt < 8; ++nt)
#pragma unroll
        for (int e = 0; e < 4; ++e) o[nt][e] = 0.f;
    float mrun0 = -1e30f, mrun1 = -1e30f, sum0 = 0.f, sum1 = 0.f;

    const int cstart = (q0 == 0) ? 4 : 0;   // first block: keys 0..127 fully masked
#pragma unroll 1
    for (int c = cstart; c < 5; ++c) {
        const uint32_t coff = (uint32_t)c * 4096;

        // ================= QK chunk: S[16,32] (S pre-scaled via Q) ==========
        float s[4][4];
#pragma unroll
        for (int t = 0; t < 4; ++t)
#pragma unroll
            for (int e = 0; e < 4; ++e) s[t][e] = 0.f;

#pragma unroll
        for (int kk = 0; kk < 4; ++kk) {
            uint32_t k0[4], k1[4];
            ldsm4(k0, akk[kk] + coff);
            ldsm4(k1, akk[kk] + coff + 2048);
            mma16816(s[0], qh[kk], k0[0], k0[1]);
            mma16816(s[1], qh[kk], k0[2], k0[3]);
            mma16816(s[2], qh[kk], k1[0], k1[1]);
            mma16816(s[3], qh[kk], k1[2], k1[3]);
        }

        // ---- prefetch all PV V-tiles now; latency overlaps the epilogue ----
        uint32_t vh[2][4][4];
#pragma unroll
        for (int kk = 0; kk < 2; ++kk)
#pragma unroll
            for (int np = 0; np < 4; ++np)
                ldsm4t(vh[kk][np], avn[np] + coff + (uint32_t)kk * 2048);

        // ================= mask + online softmax =================
        float cm0 = -1e30f, cm1 = -1e30f;
#pragma unroll
        for (int t = 0; t < 4; ++t)
#pragma unroll
            for (int e = 0; e < 2; ++e) {
                const int j = 32 * c + 8 * t + 2 * tg + e;
                s[t][e]     = (j >= jlo0 && j <= jhi0) ? s[t][e]     : -1e30f;
                s[t][2 + e] = (j >= jlo1 && j <= jhi1) ? s[t][2 + e] : -1e30f;
                cm0 = fmaxf(cm0, s[t][e]);
                cm1 = fmaxf(cm1, s[t][2 + e]);
            }
        cm0 = fmaxf(cm0, __shfl_xor_sync(0xffffffffu, cm0, 1));
        cm0 = fmaxf(cm0, __shfl_xor_sync(0xffffffffu, cm0, 2));
        cm1 = fmaxf(cm1, __shfl_xor_sync(0xffffffffu, cm1, 1));
        cm1 = fmaxf(cm1, __shfl_xor_sync(0xffffffffu, cm1, 2));

        const float mn0 = fmaxf(mrun0, cm0), mn1 = fmaxf(mrun1, cm1);
        const float corr0 = ex2(mrun0 - mn0), corr1 = ex2(mrun1 - mn1);
        mrun0 = mn0; mrun1 = mn1;

        uint32_t phi[2][4];
        float cs0 = 0.f, cs1 = 0.f;
#pragma unroll
        for (int kk = 0; kk < 2; ++kk) {
            const float p00 = ex2(s[2 * kk][0] - mn0),     p01 = ex2(s[2 * kk][1] - mn0);
            const float p10 = ex2(s[2 * kk][2] - mn1),     p11 = ex2(s[2 * kk][3] - mn1);
            const float p02 = ex2(s[2 * kk + 1][0] - mn0), p03 = ex2(s[2 * kk + 1][1] - mn0);
            const float p12 = ex2(s[2 * kk + 1][2] - mn1), p13 = ex2(s[2 * kk + 1][3] - mn1);
            cs0 += (p00 + p01) + (p02 + p03);
            cs1 += (p10 + p11) + (p12 + p13);
            phi[kk][0] = h2(p00, p01);
            phi[kk][1] = h2(p10, p11);
            phi[kk][2] = h2(p02, p03);
            phi[kk][3] = h2(p12, p13);
        }
        cs0 += __shfl_xor_sync(0xffffffffu, cs0, 1);
        cs0 += __shfl_xor_sync(0xffffffffu, cs0, 2);
        cs1 += __shfl_xor_sync(0xffffffffu, cs1, 1);
        cs1 += __shfl_xor_sync(0xffffffffu, cs1, 2);
        sum0 = sum0 * corr0 + cs0;
        sum1 = sum1 * corr1 + cs1;

#pragma unroll
        for (int nt = 0; nt < 8; ++nt) {
            o[nt][0] *= corr0; o[nt][1] *= corr0;
            o[nt][2] *= corr1; o[nt][3] *= corr1;
        }

        // ================= PV chunk: O[16,64] += P V =================
#pragma unroll
        for (int kk = 0; kk < 2; ++kk)
#pragma unroll
            for (int np = 0; np < 4; ++np) {
                mma16816(o[2 * np],     phi[kk], vh[kk][np][0], vh[kk][np][1]);
                mma16816(o[2 * np + 1], phi[kk], vh[kk][np][2], vh[kk][np][3]);
            }
    }

    // ================= normalize + store (O layout == Q layout) =================
    const float inv0 = 1.f / sum0, inv1 = 1.f / sum1;
    float* ob0 = Og + (qrow0 - Qg);
    float* ob1 = Og + (qrow1 - Qg);
#pragma unroll
    for (int nt = 0; nt < 8; ++nt) {
        const int d = nt * 8 + 2 * tg;
        *reinterpret_cast<float2*>(ob0 + d) = make_float2(o[nt][0] * inv0, o[nt][1] * inv0);
        *reinterpret_cast<float2*>(ob1 + d) = make_float2(o[nt][2] * inv1, o[nt][3] * inv1);
    }
}

} // namespace

extern "C" void kernel_launch(void* const* d_in, const int* in_sizes, int n_in,
                              void* d_out, int out_size)
{
    (void)in_sizes; (void)n_in; (void)out_size;
    const float* Q = (const float*)d_in[0];
    const float* K = (const float*)d_in[1];
    const float* V = (const float*)d_in[2];
    // d_in[3] = sinks — unused by the reference math, faithfully ignored.
    float* O = (float*)d_out;

    cudaFuncSetAttribute(swa_mma_kernel, cudaFuncAttributeMaxDynamicSharedMemorySize,
                         SMEM_BYTES);

    dim3 grid(SEQ / 32, 8, 2);
    swa_mma_kernel<<<grid, 256, SMEM_BYTES>>>(Q, K, V, O);
}